// round 11
// baseline (speedup 1.0000x reference)
#include <cuda_runtime.h>

// RoIAlign (FPN, 4 levels) + fused 2x2 stride-1 avg epilogue.
// Levels are sorted ascending within each batch, so roi j and roi 511-j
// have complementary costs. Each block processes one such PAIR (32 channels
// of each roi; 8 slices -> grid 4096), making block durations uniform for
// near-perfect wave packing while keeping 8 ch of work per warp (amortized
// setup, deep MLP). Setup for both rois runs in parallel (tid<64 -> roi A,
// tid in [128,192) -> roi B), one barrier.
// Per roi: lane l (<28) owns x-tap column l = 2*t + k. Fast path
// (rh <= 14 px): pooled row's 4 bilinear rows fit a 3-row window -> <=3
// loads. Outer loop over pooled rows, inner over 4 channels (smem
// descriptors read once per py). Epilogue: out[py-1,px] = 8-lane window
// sum (shfl_down 1,2,4) of (v[py-1]+v[py])*wcol, 1/16 folded into wcol.

namespace {
constexpr int C = 256;

__global__ __launch_bounds__(256, 4)
void roialign_kernel(const float* __restrict__ f0, const float* __restrict__ f1,
                     const float* __restrict__ f2, const float* __restrict__ f3,
                     const float* __restrict__ rois, float* __restrict__ out)
{
    const int pidx  = blockIdx.x >> 3;      // 0..511 pair index
    const int slice = blockIdx.x & 7;       // 32-channel slice
    const int b = pidx >> 8;                // batch (N=512 -> 256 pairs/batch)
    const int j = pidx & 255;
    const int roiA = (b << 9) + j;
    const int roiB = (b << 9) + 511 - j;

    __shared__ int    scol[2][32];          // column index per lane (clamped)
    __shared__ float  swx[2][32];           // x-weight per lane (0 if invalid)
    __shared__ float4 sy[2][14];            // {off0, off1 (int bits), wy0, wy1}
    __shared__ float4 spy[2][7];            // fast: {baseOff bits, w0, w1, w2}
    __shared__ int2   smeta[2];             // {lev, fast}

    const int tid = threadIdx.x;
    {
        const int half = tid >> 7;          // 0 -> roiA, 1 -> roiB
        const int st = tid & 127;
        const float* r = rois + (half ? roiB : roiA) * 7;
        const int lev = (int)r[6];
        const int Wd = 160 >> lev;
        const float scale = 8.0f / (float)(1 << lev);
        const float rh_u = fmaxf((r[4] - r[2]) * scale, 1.0f);
        const bool fast = (rh_u <= 14.0f);

        if (st < 32) {                      // x-tap setup: lane l = 2*t + k
            int l = min(st, 27);            // idle lanes alias lane 27
            int t = l >> 1, k = l & 1;
            const float c1 = r[1] * scale;
            const float c2 = r[3] * scale;
            const float bin = fmaxf(c2 - c1, 1.0f) * (1.0f / 7.0f);
            const float off = (float)(t >> 1) + ((t & 1) ? 0.75f : 0.25f);
            const float pos = c1 + off * bin;
            const bool valid = (pos >= -1.0f) && (pos <= (float)Wd);
            const float p = fminf(fmaxf(pos, 0.0f), (float)(Wd - 1));
            const float p0 = floorf(p);
            const int i0 = (int)p0;
            const int i1 = min(i0 + 1, Wd - 1);
            const float lx = p - p0;
            scol[half][st] = k ? i1 : i0;
            swx[half][st] = (st < 28 && valid) ? 0.0625f * (k ? lx : 1.0f - lx)
                                               : 0.0f;
            if (st == 0) smeta[half] = make_int2(lev, fast ? 1 : 0);
        } else if (st < 46) {               // y-sample setup: s = st - 32
            const int s = st - 32;
            const float c1 = r[2] * scale;
            const float c2 = r[4] * scale;
            const float bin = fmaxf(c2 - c1, 1.0f) * (1.0f / 7.0f);
            const float off = (float)(s >> 1) + ((s & 1) ? 0.75f : 0.25f);
            const float pos = c1 + off * bin;
            const bool valid = (pos >= -1.0f) && (pos <= (float)Wd);
            const float p = fminf(fmaxf(pos, 0.0f), (float)(Wd - 1));
            const float p0 = floorf(p);
            const int i0 = (int)p0;
            const int i1 = min(i0 + 1, Wd - 1);
            const float ly = p - p0;
            float4 v;
            v.x = __int_as_float(i0 * Wd);
            v.y = __int_as_float(i1 * Wd);
            v.z = valid ? (1.0f - ly) : 0.0f;
            v.w = valid ? ly : 0.0f;
            sy[half][s] = v;
        } else if (st < 53 && fast) {       // fast 3-row windows, py = st-46
            const int py = st - 46;
            const float c1 = r[2] * scale;
            const float c2 = r[4] * scale;
            const float bin = fmaxf(c2 - c1, 1.0f) * (1.0f / 7.0f);
            float w[3] = {0.0f, 0.0f, 0.0f};
            int base = 0;
            #pragma unroll
            for (int h = 0; h < 2; ++h) {
                const int s = 2 * py + h;
                const float off = (float)(s >> 1) + ((s & 1) ? 0.75f : 0.25f);
                const float pos = c1 + off * bin;
                const bool valid = (pos >= -1.0f) && (pos <= (float)Wd);
                const float p = fminf(fmaxf(pos, 0.0f), (float)(Wd - 1));
                const float p0 = floorf(p);
                const int i0 = (int)p0;
                const int i1 = min(i0 + 1, Wd - 1);
                const float ly = p - p0;
                if (h == 0) base = i0;      // rows monotone within the bin
                w[i0 - base] += valid ? (1.0f - ly) : 0.0f;
                w[i1 - base] += valid ? ly : 0.0f;
            }
            float4 e;
            e.x = __int_as_float(base * Wd);
            e.y = w[0]; e.z = w[1]; e.w = w[2];
            spy[half][py] = e;
        }
    }
    __syncthreads();

    const int warp = tid >> 5;
    const int lane = tid & 31;
    const bool active = (lane & 3) == 0 && lane < 24;
    const int px = lane >> 2;               // 0..5 when active
    const int cbase = slice * 32 + warp * 4;

    #pragma unroll 1
    for (int p = 0; p < 2; ++p) {
        const int roi = p ? roiB : roiA;
        const int2 meta = smeta[p];
        const int lev = meta.x;
        const bool fast = meta.y != 0;
        const int Wd = 160 >> lev;
        const int HW = Wd * Wd;
        const float* fb = (lev == 0) ? f0 : (lev == 1) ? f1
                        : (lev == 2) ? f2 : f3;
        const int mycol = scol[p][lane];
        const float wcol = swx[p][lane];
        const float* fc0 = fb + (size_t)(b * C + cbase) * HW + mycol;
        float* op0 = out + (size_t)roi * (C * 36) + cbase * 36 + px;

        float prev[4];
        #pragma unroll 1
        for (int py = 0; py < 7; ++py) {
            float v[4];
            if (fast) {
                const float4 e = spy[p][py];
                const int bo = __float_as_int(e.x);
                const bool h0 = (e.y != 0.0f);
                const bool h1 = (e.z != 0.0f);
                const bool h2 = (e.w != 0.0f);
                #pragma unroll
                for (int ch = 0; ch < 4; ++ch) {
                    const float* fc = fc0 + ch * HW;
                    float a = 0.0f;
                    if (h0) a += e.y * __ldg(fc + bo);
                    if (h1) a += e.z * __ldg(fc + bo + Wd);
                    if (h2) a += e.w * __ldg(fc + bo + 2 * Wd);
                    v[ch] = a;
                }
            } else {
                const float4 y0 = sy[p][2 * py];
                const float4 y1 = sy[p][2 * py + 1];
                const int o00 = __float_as_int(y0.x);
                const int o01 = __float_as_int(y0.y);
                const int o10 = __float_as_int(y1.x);
                const int o11 = __float_as_int(y1.y);
                #pragma unroll
                for (int ch = 0; ch < 4; ++ch) {
                    const float* fc = fc0 + ch * HW;
                    const float a00 = __ldg(fc + o00);
                    const float a01 = __ldg(fc + o01);
                    const float a10 = __ldg(fc + o10);
                    const float a11 = __ldg(fc + o11);
                    v[ch] = y0.z * a00 + y0.w * a01 + y1.z * a10 + y1.w * a11;
                }
            }
            if (py > 0) {
                #pragma unroll
                for (int ch = 0; ch < 4; ++ch) {
                    float u = (prev[ch] + v[ch]) * wcol;
                    u += __shfl_down_sync(0xFFFFFFFFu, u, 1);
                    u += __shfl_down_sync(0xFFFFFFFFu, u, 2);
                    u += __shfl_down_sync(0xFFFFFFFFu, u, 4);
                    if (active)
                        op0[ch * 36 + (py - 1) * 6] = u;
                }
            }
            #pragma unroll
            for (int ch = 0; ch < 4; ++ch) prev[ch] = v[ch];
        }
    }
}
} // namespace

extern "C" void kernel_launch(void* const* d_in, const int* in_sizes, int n_in,
                              void* d_out, int out_size) {
    const float* f0   = (const float*)d_in[0];
    const float* f1   = (const float*)d_in[1];
    const float* f2   = (const float*)d_in[2];
    const float* f3   = (const float*)d_in[3];
    const float* rois = (const float*)d_in[4];
    const int nroi = in_sizes[4] / 7;       // B*N = 1024
    roialign_kernel<<<nroi * 4, 256>>>(f0, f1, f2, f3, rois, (float*)d_out);
}